// round 2
// baseline (speedup 1.0000x reference)
#include <cuda_runtime.h>
#include <math.h>

// TopKRouter: logits = x @ gate_w^T, softmax, top-2 (+renorm), aux loss.
// T=16384 tokens, D=2048, E=64, K=2.
//
// Output layout (float32): [indices(2T) | weights(2T) | ... | aux at out_size-1]
//
// R1: LDS-bound at 137us (model-verified). Rebalance: 256 threads, thread tile
// 8 tokens x 4 experts (32 FMA per 48B LDS), W broadcast within warp,
// x token-split [0,64) + [64,128) for 2-wavefront LDS.128. FMA-pipe bound.

#define NEXP   64
#define TOPK   2
#define BK     32
#define MT     128      // tokens per block
#define NTHR   256
#define MAXBLK 512

__device__ int   g_counts[NEXP];
__device__ float g_wsum_part[MAXBLK * NEXP];
__device__ float g_z_part[MAXBLK];

__device__ __forceinline__ unsigned long long pack2(float v) {
    unsigned long long r;
    unsigned int u = __float_as_uint(v);
    asm("mov.b64 %0, {%1, %1};" : "=l"(r) : "r"(u));
    return r;
}
__device__ __forceinline__ void ffma2(unsigned long long &d,
                                      unsigned long long a,
                                      unsigned long long b) {
    asm("fma.rn.f32x2 %0, %1, %2, %0;" : "+l"(d) : "l"(a), "l"(b));
}
__device__ __forceinline__ void unpack2(unsigned long long v, float &lo, float &hi) {
    unsigned int l, h;
    asm("mov.b64 {%0, %1}, %2;" : "=r"(l), "=r"(h) : "l"(v));
    lo = __uint_as_float(l);
    hi = __uint_as_float(h);
}

__global__ __launch_bounds__(NTHR, 1)
void router_main(const float* __restrict__ X, const float* __restrict__ W,
                 float* __restrict__ out, int T, int D)
{
    __shared__ __align__(16) unsigned char smem_raw[49152];
    float* xs  = (float*)smem_raw;                                 // [2][BK][MT]
    float* wsm = (float*)(smem_raw + 2 * BK * MT * sizeof(float)); // [2][BK][NEXP]

    const int tid = threadIdx.x;
    const int tg  = tid & 15;     // token group (0..15)
    const int eg  = tid >> 4;     // expert group (0..15)
    const int e0  = eg * 4;
    const int t0  = tg * 4;       // tokens t0..t0+3 and 64+t0..64+t0+3
    const long tokBase = (long)blockIdx.x * MT;
    const int NC = D / BK;

    // staging indices: coalesced float4 LDG along D
    const int lrow = tid >> 3;    // 0..31
    const int c4   = tid & 7;     // float4 column within BK
    const int swL  = c4 * 4;      // XOR swizzle for stores

    unsigned long long acc[4][4]; // [token-pair][expert], f32x2 packed
#pragma unroll
    for (int p = 0; p < 4; p++)
#pragma unroll
        for (int j = 0; j < 4; j++) acc[p][j] = 0ull;

    float4 xreg[4];
    float4 wreg[2];
    const float* Xb = X + tokBase * D;

    // ---- prologue: load + store chunk 0 ----
#pragma unroll
    for (int i = 0; i < 4; i++)
        xreg[i] = *(const float4*)(Xb + (long)(lrow + 32 * i) * D + c4 * 4);
#pragma unroll
    for (int i = 0; i < 2; i++)
        wreg[i] = *(const float4*)(W + (long)(lrow + 32 * i) * D + c4 * 4);

    {
        float* xb2 = xs;
        float* wb2 = wsm;
#pragma unroll
        for (int i = 0; i < 4; i++) {
            int row = lrow + 32 * i;
            int col = row ^ swL;
            xb2[(swL + 0) * MT + col] = xreg[i].x;
            xb2[(swL + 1) * MT + col] = xreg[i].y;
            xb2[(swL + 2) * MT + col] = xreg[i].z;
            xb2[(swL + 3) * MT + col] = xreg[i].w;
        }
#pragma unroll
        for (int i = 0; i < 2; i++) {
            int roww = lrow + 32 * i;
            int colw = roww ^ swL;
            wb2[(swL + 0) * NEXP + colw] = wreg[i].x;
            wb2[(swL + 1) * NEXP + colw] = wreg[i].y;
            wb2[(swL + 2) * NEXP + colw] = wreg[i].z;
            wb2[(swL + 3) * NEXP + colw] = wreg[i].w;
        }
    }
    __syncthreads();

    // ---- main K loop, double buffered ----
    for (int c = 0; c < NC; ++c) {
        if (c + 1 < NC) {
            const float* xp = Xb + (c + 1) * BK;
#pragma unroll
            for (int i = 0; i < 4; i++)
                xreg[i] = *(const float4*)(xp + (long)(lrow + 32 * i) * D + c4 * 4);
#pragma unroll
            for (int i = 0; i < 2; i++)
                wreg[i] = *(const float4*)(W + (long)(lrow + 32 * i) * D + (c + 1) * BK + c4 * 4);
        }
        const float* xb = xs  + (c & 1) * BK * MT;
        const float* wb = wsm + (c & 1) * BK * NEXP;
#pragma unroll
        for (int k = 0; k < BK; k++) {
            const int sw = ((k >> 2) & 7) << 2;
            ulonglong2 xa0 = *(const ulonglong2*)(xb + k * MT + (t0 ^ sw));
            ulonglong2 xa1 = *(const ulonglong2*)(xb + k * MT + 64 + (t0 ^ sw));
            float4 wv = *(const float4*)(wb + k * NEXP + (e0 ^ sw));
            unsigned long long w0 = pack2(wv.x);
            unsigned long long w1 = pack2(wv.y);
            unsigned long long w2 = pack2(wv.z);
            unsigned long long w3 = pack2(wv.w);
            ffma2(acc[0][0], xa0.x, w0);
            ffma2(acc[0][1], xa0.x, w1);
            ffma2(acc[0][2], xa0.x, w2);
            ffma2(acc[0][3], xa0.x, w3);
            ffma2(acc[1][0], xa0.y, w0);
            ffma2(acc[1][1], xa0.y, w1);
            ffma2(acc[1][2], xa0.y, w2);
            ffma2(acc[1][3], xa0.y, w3);
            ffma2(acc[2][0], xa1.x, w0);
            ffma2(acc[2][1], xa1.x, w1);
            ffma2(acc[2][2], xa1.x, w2);
            ffma2(acc[2][3], xa1.x, w3);
            ffma2(acc[3][0], xa1.y, w0);
            ffma2(acc[3][1], xa1.y, w1);
            ffma2(acc[3][2], xa1.y, w2);
            ffma2(acc[3][3], xa1.y, w3);
        }
        if (c + 1 < NC) {
            float* xb2 = xs  + ((c + 1) & 1) * BK * MT;
            float* wb2 = wsm + ((c + 1) & 1) * BK * NEXP;
#pragma unroll
            for (int i = 0; i < 4; i++) {
                int row = lrow + 32 * i;
                int col = row ^ swL;
                xb2[(swL + 0) * MT + col] = xreg[i].x;
                xb2[(swL + 1) * MT + col] = xreg[i].y;
                xb2[(swL + 2) * MT + col] = xreg[i].z;
                xb2[(swL + 3) * MT + col] = xreg[i].w;
            }
#pragma unroll
            for (int i = 0; i < 2; i++) {
                int roww = lrow + 32 * i;
                int colw = roww ^ swL;
                wb2[(swL + 0) * NEXP + colw] = wreg[i].x;
                wb2[(swL + 1) * NEXP + colw] = wreg[i].y;
                wb2[(swL + 2) * NEXP + colw] = wreg[i].z;
                wb2[(swL + 3) * NEXP + colw] = wreg[i].w;
            }
        }
        __syncthreads();
    }

    // ---- epilogue: overlay smem ----
    float* lg       = (float*)smem_raw;                                  // [MT][65]
    float* invden_s = (float*)(smem_raw + MT * 65 * sizeof(float));      // [MT]
    float* zs       = invden_s + MT;                                     // [MT]
    int*   hist     = (int*)(zs + MT);                                   // [NEXP]
    float* colred   = (float*)(hist + NEXP);                             // [4][NEXP]

#pragma unroll
    for (int p = 0; p < 4; p++) {
        int base = (p < 2) ? (t0 + 2 * p) : (64 + t0 + 2 * (p - 2));
#pragma unroll
        for (int j = 0; j < 4; j++) {
            float lo, hi;
            unpack2(acc[p][j], lo, hi);
            lg[(base    ) * 65 + e0 + j] = lo;
            lg[(base + 1) * 65 + e0 + j] = hi;
        }
    }
    if (tid < NEXP) hist[tid] = 0;
    __syncthreads();

    if (tid < MT) {
        const int t = tid;
        float* row = lg + t * 65;
        // pass 1: max + top-2 on RAW logits (exact compares; monotone w.r.t softmax)
        float b0 = row[0], b1 = -3.0e38f;
        int   i0 = 0,      i1 = 0;
#pragma unroll 8
        for (int e = 1; e < NEXP; e++) {
            float v = row[e];
            if (v > b0) { b1 = b0; i1 = i0; b0 = v; i0 = e; }
            else if (v > b1) { b1 = v; i1 = e; }
        }
        const float m = b0;  // max logit
        // pass 2: exp + sum (store exp for P partials)
        float s = 0.f;
#pragma unroll 8
        for (int e = 0; e < NEXP; e++) {
            float v = __expf(row[e] - m);
            row[e] = v;
            s += v;
        }
        float v0 = row[i0];          // = 1.0f
        float v1 = row[i1];
        float st  = v0 + v1;
        float wn0 = __fdiv_rn(v0, st);
        float wn1 = __fdiv_rn(v1, st);
        long g = tokBase + t;
        out[2 * g]     = (float)i0;
        out[2 * g + 1] = (float)i1;
        out[2 * (long)T + 2 * g]     = wn0;
        out[2 * (long)T + 2 * g + 1] = wn1;
        invden_s[t] = __frcp_rn(s);
        float lse = m + logf(s);
        zs[t] = lse * lse;
        atomicAdd(&hist[i0], 1);
        atomicAdd(&hist[i1], 1);
    }
    __syncthreads();

    // per-block expert sums of softmax weights (deterministic order)
    {
        const int e   = tid & 63;
        const int seg = tid >> 6;  // 0..3
        float s = 0.f;
#pragma unroll 4
        for (int t = seg * 32; t < seg * 32 + 32; ++t)
            s += lg[t * 65 + e] * invden_s[t];
        colred[seg * NEXP + e] = s;
    }
    __syncthreads();
    if (tid < NEXP) {
        float p = 0.f;
#pragma unroll
        for (int sgi = 0; sgi < 4; ++sgi) p += colred[sgi * NEXP + tid];
        g_wsum_part[blockIdx.x * NEXP + tid] = p;
        atomicAdd(&g_counts[tid], hist[tid]);
        zs[tid] += zs[tid + 64];
    }
    __syncthreads();
    if (tid == 0) {
        float z = 0.f;
        for (int t = 0; t < 64; t++) z += zs[t];
        g_z_part[blockIdx.x] = z;
    }
}

__global__ void router_init() { g_counts[threadIdx.x] = 0; }

__global__ void router_finalize(float* __restrict__ out, int T, int nblk, int aux_pos)
{
    __shared__ float red[NEXP];
    const int e = threadIdx.x;
    float ws = 0.f;
    for (int b = 0; b < nblk; b++) ws += g_wsum_part[b * NEXP + e];
    float f = (float)g_counts[e] / (float)(T * TOPK);
    float P = ws / (float)T;
    red[e] = f * P;
    __syncthreads();
    if (e == 0) {
        float bal = 0.f;
        for (int i = 0; i < NEXP; i++) bal += red[i];
        bal *= (float)NEXP;
        float zsum = 0.f;
        for (int b = 0; b < nblk; b++) zsum += g_z_part[b];
        float z = zsum / (float)T;
        out[aux_pos] = 0.01f * bal + 0.001f * z;
    }
}

extern "C" void kernel_launch(void* const* d_in, const int* in_sizes, int n_in,
                              void* d_out, int out_size)
{
    const float* X = (const float*)d_in[0];
    const float* W = (const float*)d_in[1];
    float* out = (float*)d_out;

    const int D = in_sizes[1] / NEXP;     // 2048
    const int T = in_sizes[0] / D;        // 16384
    const int nblk = T / MT;              // 128

    router_init<<<1, NEXP>>>();
    router_main<<<nblk, NTHR>>>(X, W, out, T, D);
    router_finalize<<<1, NEXP>>>(out, T, nblk, out_size - 1);
}